// round 14
// baseline (speedup 1.0000x reference)
#include <cuda_runtime.h>
#include <cuda_bf16.h>
#include <cstdint>

#define B_    4
#define T_    4096
#define E_    1024
#define MROWS (B_ * T_)
#define CL2   0.045084220f   // (1/32) * log2(e)

// hi/lo bf16 planes
__device__ __nv_bfloat16 g_qh[MROWS * 64], g_ql[MROWS * 64];
__device__ __nv_bfloat16 g_kh[MROWS * 64], g_kl[MROWS * 64];
__device__ __nv_bfloat16 g_vth[B_ * 64 * T_], g_vtl[B_ * 64 * T_];
// pre-split W planes: rows 0-63 = Wq, 64-127 = Wk, 128-191 = Wv
__device__ __nv_bfloat16 g_wh[192 * E_], g_wl[192 * E_];
// split-K partials: slot = (b*64 + qt)*8 + c
__device__ float g_po[2048 * 64 * 64];
__device__ float g_pl[2048 * 64];

// ---------------------------------------------------------------------------
__device__ __forceinline__ void hmma(float* c, const uint32_t* a,
                                     uint32_t b0, uint32_t b1) {
    asm volatile("mma.sync.aligned.m16n8k16.row.col.f32.bf16.bf16.f32 "
                 "{%0,%1,%2,%3}, {%4,%5,%6,%7}, {%8,%9}, {%0,%1,%2,%3};"
                 : "+f"(c[0]), "+f"(c[1]), "+f"(c[2]), "+f"(c[3])
                 : "r"(a[0]), "r"(a[1]), "r"(a[2]), "r"(a[3]),
                   "r"(b0), "r"(b1));
}
__device__ __forceinline__ void ldmx4(uint32_t* r, const void* p) {
    uint32_t a = (uint32_t)__cvta_generic_to_shared(p);
    asm volatile("ldmatrix.sync.aligned.m8n8.x4.shared.b16 {%0,%1,%2,%3}, [%4];"
                 : "=r"(r[0]), "=r"(r[1]), "=r"(r[2]), "=r"(r[3]) : "r"(a));
}
__device__ __forceinline__ uint32_t bfpack(float a, float b) {
    __nv_bfloat162 h(__float2bfloat16(a), __float2bfloat16(b));
    return *(uint32_t*)&h;
}
__device__ __forceinline__ float bflo(float x) {
    return x - __bfloat162float(__float2bfloat16(x));
}
__device__ __forceinline__ float ex2(float x) {
    float y; asm("ex2.approx.f32 %0, %1;" : "=f"(y) : "f"(x)); return y;
}
__device__ __forceinline__ void cpa(void* dst, const void* src) {
    uint32_t d = (uint32_t)__cvta_generic_to_shared(dst);
    asm volatile("cp.async.cg.shared.global [%0], [%1], 16;"
                 :: "r"(d), "l"(src) : "memory");
}
#define CP_COMMIT() asm volatile("cp.async.commit_group;" ::: "memory")
#define CP_WAIT0()  asm volatile("cp.async.wait_group 0;" ::: "memory")
#define CP_WAIT1()  asm volatile("cp.async.wait_group 1;" ::: "memory")

// ---------------------------------------------------------------------------
// W pre-split: 192 rows x 1024. grid 192, 256 threads.
// ---------------------------------------------------------------------------
__global__ __launch_bounds__(256) void wsplit_kernel(
    const float* __restrict__ Wq, const float* __restrict__ Wk,
    const float* __restrict__ Wv)
{
    const int r = blockIdx.x, c = threadIdx.x * 4;
    const float* W = (r < 64) ? Wq : (r < 128) ? Wk : Wv;
    float4 v = *(const float4*)&W[(size_t)(r & 63) * E_ + c];
    *(uint2*)&g_wh[r * E_ + c] =
        make_uint2(bfpack(v.x, v.y), bfpack(v.z, v.w));
    *(uint2*)&g_wl[r * E_ + c] =
        make_uint2(bfpack(bflo(v.x), bflo(v.y)), bfpack(bflo(v.z), bflo(v.w)));
}

// ---------------------------------------------------------------------------
// Merged projection, cp.async double-buffered. grid 128, 256 threads (8 warps).
// Warp owns 16 rows x all 192 out cols. K-chunks of 64.
// smem: Araw[2] 128x68 fp32, Bh/Bl[2] 192x72 bf16 = 180224 B total.
// Register-limited to 1 CTA/SM, so big smem is free; prefetch of chunk ch+1
// overlaps MMA of chunk ch. A converted fp32->hi/lo in registers at frag load.
// ---------------------------------------------------------------------------
#define PAW 68
#define PST 72
#define ARAW_B 34816
#define BPLANE 27648
#define PSMEM (2 * ARAW_B + 4 * BPLANE)

__global__ __launch_bounds__(256) void proj_kernel(const float* __restrict__ emb)
{
    extern __shared__ char psm[];
    float* Araw0 = (float*)psm;
    float* Araw1 = (float*)(psm + ARAW_B);
    __nv_bfloat16* Bbase = (__nv_bfloat16*)(psm + 2 * ARAW_B);

    const int tid = threadIdx.x, lane = tid & 31, wid = tid >> 5;
    const int gq = lane >> 2, tg = lane & 3;
    const int row0 = blockIdx.x * 128;

    float acc[24][4];
    #pragma unroll
    for (int j = 0; j < 24; j++)
        #pragma unroll
        for (int e = 0; e < 4; e++) acc[j][e] = 0.0f;

    auto issue = [&](int ch) {
        const int bsel = ch & 1;
        float* Ar = bsel ? Araw1 : Araw0;
        __nv_bfloat16* Bh = Bbase + bsel * 2 * (192 * PST);
        __nv_bfloat16* Bl = Bh + 192 * PST;
        const int k0 = ch * 64;
        #pragma unroll
        for (int it = 0; it < 8; it++) {
            int idx = tid + it * 256;
            int r = idx >> 4, f = idx & 15;
            cpa(&Ar[r * PAW + f * 4],
                &emb[(size_t)(row0 + r) * E_ + k0 + f * 4]);
        }
        #pragma unroll
        for (int it = 0; it < 6; it++) {
            int idx = tid + it * 256;
            int r = idx >> 3, f = idx & 7;
            cpa(&Bh[r * PST + f * 8], &g_wh[(size_t)r * E_ + k0 + f * 8]);
            cpa(&Bl[r * PST + f * 8], &g_wl[(size_t)r * E_ + k0 + f * 8]);
        }
    };

    issue(0);
    CP_COMMIT();

    for (int ch = 0; ch < 16; ch++) {
        if (ch < 15) {
            issue(ch + 1);
            CP_COMMIT();
            CP_WAIT1();
        } else {
            CP_WAIT0();
        }
        __syncthreads();

        const int bsel = ch & 1;
        const float* Ar = bsel ? Araw1 : Araw0;
        const __nv_bfloat16* Bh = Bbase + bsel * 2 * (192 * PST);
        const __nv_bfloat16* Bl = Bh + 192 * PST;
        const int rr = wid * 16 + gq;

        #pragma unroll
        for (int kc = 0; kc < 4; kc++) {
            const int c = kc * 16 + tg * 2;
            float2 x0 = *(const float2*)&Ar[rr * PAW + c];
            float2 x1 = *(const float2*)&Ar[(rr + 8) * PAW + c];
            float2 x2 = *(const float2*)&Ar[rr * PAW + c + 8];
            float2 x3 = *(const float2*)&Ar[(rr + 8) * PAW + c + 8];
            uint32_t ah[4], al[4];
            ah[0] = bfpack(x0.x, x0.y);  al[0] = bfpack(bflo(x0.x), bflo(x0.y));
            ah[1] = bfpack(x1.x, x1.y);  al[1] = bfpack(bflo(x1.x), bflo(x1.y));
            ah[2] = bfpack(x2.x, x2.y);  al[2] = bfpack(bflo(x2.x), bflo(x2.y));
            ah[3] = bfpack(x3.x, x3.y);  al[3] = bfpack(bflo(x3.x), bflo(x3.y));
            #pragma unroll
            for (int j = 0; j < 24; j++) {
                const int bn = (j * 8 + gq) * PST + c;
                uint32_t bh0 = *(const uint32_t*)&Bh[bn];
                uint32_t bh1 = *(const uint32_t*)&Bh[bn + 8];
                uint32_t bl0 = *(const uint32_t*)&Bl[bn];
                uint32_t bl1 = *(const uint32_t*)&Bl[bn + 8];
                hmma(acc[j], ah, bh0, bh1);
                hmma(acc[j], ah, bl0, bl1);
                hmma(acc[j], al, bh0, bh1);
            }
        }
        __syncthreads();
    }

    // Epilogue
    #pragma unroll
    for (int half = 0; half < 2; half++) {
        const int row = row0 + wid * 16 + gq + half * 8;
        const int b = row >> 12, t = row & (T_ - 1);
        #pragma unroll
        for (int j = 0; j < 24; j++) {
            const int wsel = j >> 3;
            const int d = (j & 7) * 8 + tg * 2;
            const float x0 = acc[j][half * 2 + 0];
            const float x1 = acc[j][half * 2 + 1];
            if (wsel < 2) {
                __nv_bfloat16* gh = (wsel == 0) ? g_qh : g_kh;
                __nv_bfloat16* gl = (wsel == 0) ? g_ql : g_kl;
                *(uint32_t*)&gh[(size_t)row * 64 + d] = bfpack(x0, x1);
                *(uint32_t*)&gl[(size_t)row * 64 + d] = bfpack(bflo(x0), bflo(x1));
            } else {
                g_vth[(size_t)(b * 64 + d) * T_ + t]     = __float2bfloat16(x0);
                g_vth[(size_t)(b * 64 + d + 1) * T_ + t] = __float2bfloat16(x1);
                g_vtl[(size_t)(b * 64 + d) * T_ + t]     = __float2bfloat16(bflo(x0));
                g_vtl[(size_t)(b * 64 + d + 1) * T_ + t] = __float2bfloat16(bflo(x1));
            }
        }
    }
}

// ---------------------------------------------------------------------------
// Flash attention, split-K units, m=0 softmax, cp.async double-buffered K/V,
// ldmatrix.x4 B-operand fragment loads (R7-verified mapping).
// grid 1152 = 4 x 288. Unit = (b, 64-row q-block qt, chunk c of <=8 key
// tiles of 64). 128 threads (4 warps), warp = 16 rows.
// smem: 2 bufs x 4 planes x 64x72 bf16 = 73728 B (dynamic); 3 CTAs/SM.
// ---------------------------------------------------------------------------
#define KST   72
#define TILEB (64 * KST)

__device__ __forceinline__ void attn_issue(__nv_bfloat16* buf, int b, size_t bT,
                                           int k0, int tid) {
    __nv_bfloat16* Kh = buf;
    __nv_bfloat16* Kl = buf + TILEB;
    __nv_bfloat16* Vh = buf + 2 * TILEB;
    __nv_bfloat16* Vl = buf + 3 * TILEB;
    #pragma unroll
    for (int it = 0; it < 4; it++) {
        int idx = tid + it * 128;
        int r = idx >> 3, f = idx & 7;
        cpa(&Kh[r * KST + f * 8], &g_kh[(bT + k0 + r) * 64 + f * 8]);
        cpa(&Kl[r * KST + f * 8], &g_kl[(bT + k0 + r) * 64 + f * 8]);
        cpa(&Vh[r * KST + f * 8], &g_vth[(size_t)(b * 64 + r) * T_ + k0 + f * 8]);
        cpa(&Vl[r * KST + f * 8], &g_vtl[(size_t)(b * 64 + r) * T_ + k0 + f * 8]);
    }
}

__global__ __launch_bounds__(128) void attn_kernel()
{
    extern __shared__ __nv_bfloat16 smd[];

    const int tid = threadIdx.x, lane = tid & 31, wid = tid >> 5;
    const int gq = lane >> 2, tg = lane & 3;
    const int l7 = lane & 7;

    // decode unit
    const int u = blockIdx.x;
    const int b = u / 288;
    const int r = u - b * 288;
    int gg = 0;
    #pragma unroll
    for (int i = 1; i < 8; i++) if (r >= 4 * i * (i + 1)) gg = i;
    const int off = r - 4 * gg * (gg + 1);
    const int blk = off / (gg + 1);
    const int c   = off - blk * (gg + 1);
    const int qt  = 8 * gg + blk;
    const int t0  = c * 8;
    const int t1  = min(t0 + 8, qt + 1);
    const int q0  = qt * 64;
    const size_t bT = (size_t)b * T_;
    const int rloc = wid * 16 + gq;
    const int r0 = q0 + rloc;

    // first tile load in flight while Q fragments come from L2
    attn_issue(smd, b, bT, t0 * 64, tid);
    CP_COMMIT();

    // Hoist Q fragments (hi and lo)
    uint32_t qfh[4][4], qfl[4][4];
    #pragma unroll
    for (int kc = 0; kc < 4; kc++) {
        const int cc = kc * 16 + tg * 2;
        const size_t p0 = (bT + r0) * 64 + cc;
        const size_t p1 = (bT + r0 + 8) * 64 + cc;
        qfh[kc][0] = *(const uint32_t*)&g_qh[p0];
        qfh[kc][1] = *(const uint32_t*)&g_qh[p1];
        qfh[kc][2] = *(const uint32_t*)&g_qh[p0 + 8];
        qfh[kc][3] = *(const uint32_t*)&g_qh[p1 + 8];
        qfl[kc][0] = *(const uint32_t*)&g_ql[p0];
        qfl[kc][1] = *(const uint32_t*)&g_ql[p1];
        qfl[kc][2] = *(const uint32_t*)&g_ql[p0 + 8];
        qfl[kc][3] = *(const uint32_t*)&g_ql[p1 + 8];
    }

    float O[8][4];
    #pragma unroll
    for (int j = 0; j < 8; j++)
        #pragma unroll
        for (int e = 0; e < 4; e++) O[j][e] = 0.0f;
    float l0 = 0.0f, l1 = 0.0f;

    for (int t = t0; t < t1; t++) {
        const int cur = (t - t0) & 1;
        const __nv_bfloat16* buf = smd + cur * 4 * TILEB;
        const __nv_bfloat16* Kh = buf;
        const __nv_bfloat16* Kl = buf + TILEB;
        const __nv_bfloat16* Vh = buf + 2 * TILEB;
        const __nv_bfloat16* Vl = buf + 3 * TILEB;
        const int k0 = t * 64;

        if (t + 1 < t1) {
            attn_issue(smd + (cur ^ 1) * 4 * TILEB, b, bT, (t + 1) * 64, tid);
            CP_COMMIT();
            CP_WAIT1();
        } else {
            CP_WAIT0();
        }
        __syncthreads();

        // GEMM1: S = Q . K^T (3 hi/lo terms), B frags via ldmatrix.x4
        float S[8][4];
        #pragma unroll
        for (int j = 0; j < 8; j++)
            #pragma unroll
            for (int e = 0; e < 4; e++) S[j][e] = 0.0f;
        #pragma unroll
        for (int j = 0; j < 8; j++) {
            const int bo = (j * 8 + l7) * KST + (lane >> 3) * 8;
            uint32_t bh[8], bl[8];
            ldmx4(bh, &Kh[bo]); ldmx4(bh + 4, &Kh[bo + 32]);
            ldmx4(bl, &Kl[bo]); ldmx4(bl + 4, &Kl[bo + 32]);
            #pragma unroll
            for (int kc = 0; kc < 4; kc++) {
                hmma(S[j], qfh[kc], bh[2 * kc], bh[2 * kc + 1]);
                hmma(S[j], qfh[kc], bl[2 * kc], bl[2 * kc + 1]);
                hmma(S[j], qfl[kc], bh[2 * kc], bh[2 * kc + 1]);
            }
        }

        // Softmax with fixed shift m=0 (scores*CL2 sigma ~0.36; exp2 cannot
        // overflow; softmax shift-invariant -> exact)
        const bool diag = (t == qt);
        float rs0 = 0.0f, rs1 = 0.0f;
        #pragma unroll
        for (int j = 0; j < 8; j++) {
            #pragma unroll
            for (int e = 0; e < 2; e++) {
                const int kg = k0 + j * 8 + tg * 2 + e;
                float z0 = S[j][e] * CL2;
                float z1 = S[j][2 + e] * CL2;
                if (diag) {
                    if (kg > r0)     z0 = -1e30f;
                    if (kg > r0 + 8) z1 = -1e30f;
                }
                float p0 = ex2(z0);
                float p1 = ex2(z1);
                S[j][e] = p0; S[j][2 + e] = p1;
                rs0 += p0; rs1 += p1;
            }
        }
        l0 += rs0;
        l1 += rs1;

        // P accum -> A fragments (hi/lo)
        uint32_t pfh[4][4], pfl[4][4];
        #pragma unroll
        for (int kc = 0; kc < 4; kc++) {
            const int j0 = 2 * kc, j1 = 2 * kc + 1;
            pfh[kc][0] = bfpack(S[j0][0], S[j0][1]);
            pfh[kc][1] = bfpack(S[j0][2], S[j0][3]);
            pfh[kc][2] = bfpack(S[j1][0], S[j1][1]);
            pfh[kc][3] = bfpack(S[j1][2], S[j1][3]);
            pfl[kc][0] = bfpack(bflo(S[j0][0]), bflo(S[j0][1]));
            pfl[kc][1] = bfpack(bflo(S[j0][2]), bflo(S[j0][3]));
            pfl[kc][2] = bfpack(bflo(S[j1][0]), bflo(S[j1][1]));
            pfl[kc][3] = bfpack(bflo(S[j1][2]), bflo(S[j1][3]));
        }

        // GEMM2: O += P . V (3 hi/lo terms), B frags via ldmatrix.x4
        #pragma unroll
        for (int j = 0; j < 8; j++) {
            const int bo = (j * 8 + l7) * KST + (lane >> 3) * 8;
            uint32_t vh[8], vl[8];
            ldmx4(vh, &Vh[bo]); ldmx4(vh + 4, &Vh[bo + 32]);
            ldmx4(vl, &Vl[bo]); ldmx4(vl + 4, &Vl[bo + 32]);
            #pragma unroll
            for (int kc = 0; kc < 4; kc++) {
                hmma(O[j], pfh[kc], vh[2 * kc], vh[2 * kc + 1]);
                hmma(O[j], pfh[kc], vl[2 * kc], vl[2 * kc + 1]);
                hmma(O[j], pfl[kc], vh[2 * kc], vh[2 * kc + 1]);
            }
        }
        __syncthreads();   // reads of buf done before it is refilled
    }

    // sum l across the 4 quad lanes
    l0 += __shfl_xor_sync(0xffffffffu, l0, 1);
    l0 += __shfl_xor_sync(0xffffffffu, l0, 2);
    l1 += __shfl_xor_sync(0xffffffffu, l1, 1);
    l1 += __shfl_xor_sync(0xffffffffu, l1, 2);

    // Write partial
    const int slot = (b * 64 + qt) * 8 + c;
    float* po = g_po + (size_t)slot * 4096;
    #pragma unroll
    for (int j = 0; j < 8; j++) {
        const int d = j * 8 + tg * 2;
        *(float2*)&po[rloc * 64 + d]       = make_float2(O[j][0], O[j][1]);
        *(float2*)&po[(rloc + 8) * 64 + d] = make_float2(O[j][2], O[j][3]);
    }
    if (tg == 0) {
        g_pl[slot * 64 + rloc]     = l0;
        g_pl[slot * 64 + rloc + 8] = l1;
    }
}

// ---------------------------------------------------------------------------
// Combine: grid (64, 4), 256 threads. Thread = (row, 16-col segment).
// ---------------------------------------------------------------------------
__global__ __launch_bounds__(256) void combine_kernel(float* __restrict__ out)
{
    const int qt = blockIdx.x, b = blockIdx.y;
    const int nc = (qt >> 3) + 1;
    const int tid = threadIdx.x;
    const int row = tid >> 2, seg = (tid & 3) * 16;
    const int bs = (b * 64 + qt) * 8;

    float L = 0.0f;
    float acc[16];
    #pragma unroll
    for (int e = 0; e < 16; e++) acc[e] = 0.0f;

    for (int c = 0; c < nc; c++) {
        L += g_pl[(bs + c) * 64 + row];
        const float* p = g_po + ((size_t)(bs + c) * 64 + row) * 64 + seg;
        #pragma unroll
        for (int e = 0; e < 16; e += 4) {
            float4 v = *(const float4*)(p + e);
            acc[e]     += v.x;
            acc[e + 1] += v.y;
            acc[e + 2] += v.z;
            acc[e + 3] += v.w;
        }
    }
    const float inv = 1.0f / L;
    float* q = out + ((size_t)b * T_ + qt * 64 + row) * 64 + seg;
    #pragma unroll
    for (int e = 0; e < 16; e += 4)
        *(float4*)(q + e) = make_float4(acc[e] * inv, acc[e + 1] * inv,
                                        acc[e + 2] * inv, acc[e + 3] * inv);
}

// ---------------------------------------------------------------------------
extern "C" void kernel_launch(void* const* d_in, const int* in_sizes, int n_in,
                              void* d_out, int out_size)
{
    const float* emb = (const float*)d_in[0];
    const float* Wq  = (const float*)d_in[1];
    const float* Wk  = (const float*)d_in[2];
    const float* Wv  = (const float*)d_in[3];
    float* out = (float*)d_out;

    wsplit_kernel<<<192, 256>>>(Wq, Wk, Wv);

    cudaFuncSetAttribute(proj_kernel, cudaFuncAttributeMaxDynamicSharedMemorySize,
                         PSMEM);
    proj_kernel<<<128, 256, PSMEM>>>(emb);

    const int asmem = 2 * 4 * TILEB * (int)sizeof(__nv_bfloat16);
    cudaFuncSetAttribute(attn_kernel, cudaFuncAttributeMaxDynamicSharedMemorySize,
                         asmem);
    attn_kernel<<<4 * 288, 128, asmem>>>();

    dim3 cg(64, B_, 1);
    combine_kernel<<<cg, 256>>>(out);
}

// round 15
// speedup vs baseline: 1.4441x; 1.4441x over previous
#include <cuda_runtime.h>
#include <cuda_bf16.h>
#include <cuda_fp16.h>
#include <cstdint>

#define B_    4
#define T_    4096
#define E_    1024
#define MROWS (B_ * T_)
#define CL2   0.045084220f   // (1/32) * log2(e)

// fp16 planes for attention (single precision pass)
__device__ __half g_qf[MROWS * 64];
__device__ __half g_kf[MROWS * 64];
__device__ __half g_vtf[B_ * 64 * T_];   // V transposed [b][d][t]
// pre-split W planes (bf16 hi/lo): rows 0-63 = Wq, 64-127 = Wk, 128-191 = Wv
__device__ __nv_bfloat16 g_wh[192 * E_], g_wl[192 * E_];
// split-K partials: slot = (b*64 + qt)*8 + c
__device__ float g_po[2048 * 64 * 64];
__device__ float g_pl[2048 * 64];

// ---------------------------------------------------------------------------
__device__ __forceinline__ void hmma_bf16(float* c, const uint32_t* a,
                                          uint32_t b0, uint32_t b1) {
    asm volatile("mma.sync.aligned.m16n8k16.row.col.f32.bf16.bf16.f32 "
                 "{%0,%1,%2,%3}, {%4,%5,%6,%7}, {%8,%9}, {%0,%1,%2,%3};"
                 : "+f"(c[0]), "+f"(c[1]), "+f"(c[2]), "+f"(c[3])
                 : "r"(a[0]), "r"(a[1]), "r"(a[2]), "r"(a[3]),
                   "r"(b0), "r"(b1));
}
__device__ __forceinline__ void hmma_f16(float* c, const uint32_t* a,
                                         uint32_t b0, uint32_t b1) {
    asm volatile("mma.sync.aligned.m16n8k16.row.col.f32.f16.f16.f32 "
                 "{%0,%1,%2,%3}, {%4,%5,%6,%7}, {%8,%9}, {%0,%1,%2,%3};"
                 : "+f"(c[0]), "+f"(c[1]), "+f"(c[2]), "+f"(c[3])
                 : "r"(a[0]), "r"(a[1]), "r"(a[2]), "r"(a[3]),
                   "r"(b0), "r"(b1));
}
__device__ __forceinline__ uint32_t bfpack(float a, float b) {
    __nv_bfloat162 h(__float2bfloat16(a), __float2bfloat16(b));
    return *(uint32_t*)&h;
}
__device__ __forceinline__ uint32_t hpack(float a, float b) {
    __half2 h = __floats2half2_rn(a, b);
    return *(uint32_t*)&h;
}
__device__ __forceinline__ float bflo(float x) {
    return x - __bfloat162float(__float2bfloat16(x));
}
__device__ __forceinline__ float ex2(float x) {
    float y; asm("ex2.approx.f32 %0, %1;" : "=f"(y) : "f"(x)); return y;
}
__device__ __forceinline__ void cpa(void* dst, const void* src) {
    uint32_t d = (uint32_t)__cvta_generic_to_shared(dst);
    asm volatile("cp.async.cg.shared.global [%0], [%1], 16;"
                 :: "r"(d), "l"(src) : "memory");
}
#define CP_COMMIT() asm volatile("cp.async.commit_group;" ::: "memory")
#define CP_WAIT0()  asm volatile("cp.async.wait_group 0;" ::: "memory")
#define CP_WAIT1()  asm volatile("cp.async.wait_group 1;" ::: "memory")

// ---------------------------------------------------------------------------
// W pre-split: 192 rows x 1024. grid 192, 256 threads.
// ---------------------------------------------------------------------------
__global__ __launch_bounds__(256) void wsplit_kernel(
    const float* __restrict__ Wq, const float* __restrict__ Wk,
    const float* __restrict__ Wv)
{
    const int r = blockIdx.x, c = threadIdx.x * 4;
    const float* W = (r < 64) ? Wq : (r < 128) ? Wk : Wv;
    float4 v = *(const float4*)&W[(size_t)(r & 63) * E_ + c];
    *(uint2*)&g_wh[r * E_ + c] =
        make_uint2(bfpack(v.x, v.y), bfpack(v.z, v.w));
    *(uint2*)&g_wl[r * E_ + c] =
        make_uint2(bfpack(bflo(v.x), bflo(v.y)), bfpack(bflo(v.z), bflo(v.w)));
}

// ---------------------------------------------------------------------------
// Merged projection, cp.async double-buffered (unchanged, bf16 3-term exact).
// grid 128, 256 threads. Epilogue now emits fp16 single planes.
// ---------------------------------------------------------------------------
#define PAW 68
#define PST 72
#define ARAW_B 34816
#define BPLANE 27648
#define PSMEM (2 * ARAW_B + 4 * BPLANE)

__global__ __launch_bounds__(256) void proj_kernel(const float* __restrict__ emb)
{
    extern __shared__ char psm[];
    float* Araw0 = (float*)psm;
    float* Araw1 = (float*)(psm + ARAW_B);
    __nv_bfloat16* Bbase = (__nv_bfloat16*)(psm + 2 * ARAW_B);

    const int tid = threadIdx.x, lane = tid & 31, wid = tid >> 5;
    const int gq = lane >> 2, tg = lane & 3;
    const int row0 = blockIdx.x * 128;

    float acc[24][4];
    #pragma unroll
    for (int j = 0; j < 24; j++)
        #pragma unroll
        for (int e = 0; e < 4; e++) acc[j][e] = 0.0f;

    auto issue = [&](int ch) {
        const int bsel = ch & 1;
        float* Ar = bsel ? Araw1 : Araw0;
        __nv_bfloat16* Bh = Bbase + bsel * 2 * (192 * PST);
        __nv_bfloat16* Bl = Bh + 192 * PST;
        const int k0 = ch * 64;
        #pragma unroll
        for (int it = 0; it < 8; it++) {
            int idx = tid + it * 256;
            int r = idx >> 4, f = idx & 15;
            cpa(&Ar[r * PAW + f * 4],
                &emb[(size_t)(row0 + r) * E_ + k0 + f * 4]);
        }
        #pragma unroll
        for (int it = 0; it < 6; it++) {
            int idx = tid + it * 256;
            int r = idx >> 3, f = idx & 7;
            cpa(&Bh[r * PST + f * 8], &g_wh[(size_t)r * E_ + k0 + f * 8]);
            cpa(&Bl[r * PST + f * 8], &g_wl[(size_t)r * E_ + k0 + f * 8]);
        }
    };

    issue(0);
    CP_COMMIT();

    for (int ch = 0; ch < 16; ch++) {
        if (ch < 15) {
            issue(ch + 1);
            CP_COMMIT();
            CP_WAIT1();
        } else {
            CP_WAIT0();
        }
        __syncthreads();

        const int bsel = ch & 1;
        const float* Ar = bsel ? Araw1 : Araw0;
        const __nv_bfloat16* Bh = Bbase + bsel * 2 * (192 * PST);
        const __nv_bfloat16* Bl = Bh + 192 * PST;
        const int rr = wid * 16 + gq;

        #pragma unroll
        for (int kc = 0; kc < 4; kc++) {
            const int c = kc * 16 + tg * 2;
            float2 x0 = *(const float2*)&Ar[rr * PAW + c];
            float2 x1 = *(const float2*)&Ar[(rr + 8) * PAW + c];
            float2 x2 = *(const float2*)&Ar[rr * PAW + c + 8];
            float2 x3 = *(const float2*)&Ar[(rr + 8) * PAW + c + 8];
            uint32_t ah[4], al[4];
            ah[0] = bfpack(x0.x, x0.y);  al[0] = bfpack(bflo(x0.x), bflo(x0.y));
            ah[1] = bfpack(x1.x, x1.y);  al[1] = bfpack(bflo(x1.x), bflo(x1.y));
            ah[2] = bfpack(x2.x, x2.y);  al[2] = bfpack(bflo(x2.x), bflo(x2.y));
            ah[3] = bfpack(x3.x, x3.y);  al[3] = bfpack(bflo(x3.x), bflo(x3.y));
            #pragma unroll
            for (int j = 0; j < 24; j++) {
                const int bn = (j * 8 + gq) * PST + c;
                uint32_t bh0 = *(const uint32_t*)&Bh[bn];
                uint32_t bh1 = *(const uint32_t*)&Bh[bn + 8];
                uint32_t bl0 = *(const uint32_t*)&Bl[bn];
                uint32_t bl1 = *(const uint32_t*)&Bl[bn + 8];
                hmma_bf16(acc[j], ah, bh0, bh1);
                hmma_bf16(acc[j], ah, bl0, bl1);
                hmma_bf16(acc[j], al, bh0, bh1);
            }
        }
        __syncthreads();
    }

    // Epilogue: fp16 planes for attention
    #pragma unroll
    for (int half = 0; half < 2; half++) {
        const int row = row0 + wid * 16 + gq + half * 8;
        const int b = row >> 12, t = row & (T_ - 1);
        #pragma unroll
        for (int j = 0; j < 24; j++) {
            const int wsel = j >> 3;
            const int d = (j & 7) * 8 + tg * 2;
            const float x0 = acc[j][half * 2 + 0];
            const float x1 = acc[j][half * 2 + 1];
            if (wsel < 2) {
                __half* gf = (wsel == 0) ? g_qf : g_kf;
                *(uint32_t*)&gf[(size_t)row * 64 + d] = hpack(x0, x1);
            } else {
                g_vtf[(size_t)(b * 64 + d) * T_ + t]     = __float2half(x0);
                g_vtf[(size_t)(b * 64 + d + 1) * T_ + t] = __float2half(x1);
            }
        }
    }
}

// ---------------------------------------------------------------------------
// Flash attention, split-K units, m=0 softmax, single-pass fp16 MMA.
// grid 1152 = 4 x 288. Unit = (b, 64-row q-block qt, chunk c of <=8 key
// tiles of 64). 128 threads (4 warps), warp = 16 rows.
// smem: 2 bufs x 2 planes (Kf, Vf) x 64x72 fp16 = 36864 B dynamic.
// ---------------------------------------------------------------------------
#define KST   72
#define TILEB (64 * KST)

__device__ __forceinline__ void attn_issue(__half* buf, int b, size_t bT,
                                           int k0, int tid) {
    __half* Kf = buf;
    __half* Vf = buf + TILEB;
    #pragma unroll
    for (int it = 0; it < 4; it++) {
        int idx = tid + it * 128;
        int r = idx >> 3, f = idx & 7;
        cpa(&Kf[r * KST + f * 8], &g_kf[(bT + k0 + r) * 64 + f * 8]);
        cpa(&Vf[r * KST + f * 8], &g_vtf[(size_t)(b * 64 + r) * T_ + k0 + f * 8]);
    }
}

__global__ __launch_bounds__(128) void attn_kernel()
{
    extern __shared__ __half smd[];

    const int tid = threadIdx.x, lane = tid & 31, wid = tid >> 5;
    const int gq = lane >> 2, tg = lane & 3;

    // decode unit
    const int u = blockIdx.x;
    const int b = u / 288;
    const int r = u - b * 288;
    int gg = 0;
    #pragma unroll
    for (int i = 1; i < 8; i++) if (r >= 4 * i * (i + 1)) gg = i;
    const int off = r - 4 * gg * (gg + 1);
    const int blk = off / (gg + 1);
    const int c   = off - blk * (gg + 1);
    const int qt  = 8 * gg + blk;
    const int t0  = c * 8;
    const int t1  = min(t0 + 8, qt + 1);
    const int q0  = qt * 64;
    const size_t bT = (size_t)b * T_;
    const int rloc = wid * 16 + gq;
    const int r0 = q0 + rloc;

    attn_issue(smd, b, bT, t0 * 64, tid);
    CP_COMMIT();

    // Hoist Q fragments (fp16, single)
    uint32_t qf[4][4];
    #pragma unroll
    for (int kc = 0; kc < 4; kc++) {
        const int cc = kc * 16 + tg * 2;
        const size_t p0 = (bT + r0) * 64 + cc;
        const size_t p1 = (bT + r0 + 8) * 64 + cc;
        qf[kc][0] = *(const uint32_t*)&g_qf[p0];
        qf[kc][1] = *(const uint32_t*)&g_qf[p1];
        qf[kc][2] = *(const uint32_t*)&g_qf[p0 + 8];
        qf[kc][3] = *(const uint32_t*)&g_qf[p1 + 8];
    }

    float O[8][4];
    #pragma unroll
    for (int j = 0; j < 8; j++)
        #pragma unroll
        for (int e = 0; e < 4; e++) O[j][e] = 0.0f;
    float l0 = 0.0f, l1 = 0.0f;

    for (int t = t0; t < t1; t++) {
        const int cur = (t - t0) & 1;
        const __half* buf = smd + cur * 2 * TILEB;
        const __half* Kf = buf;
        const __half* Vf = buf + TILEB;
        const int k0 = t * 64;

        if (t + 1 < t1) {
            attn_issue(smd + (cur ^ 1) * 2 * TILEB, b, bT, (t + 1) * 64, tid);
            CP_COMMIT();
            CP_WAIT1();
        } else {
            CP_WAIT0();
        }
        __syncthreads();

        // GEMM1: S = Q . K^T (single fp16 pass)
        float S[8][4];
        #pragma unroll
        for (int j = 0; j < 8; j++)
            #pragma unroll
            for (int e = 0; e < 4; e++) S[j][e] = 0.0f;
        #pragma unroll
        for (int kc = 0; kc < 4; kc++) {
            const int cc = kc * 16 + tg * 2;
            #pragma unroll
            for (int j = 0; j < 8; j++) {
                const int bn = (j * 8 + gq) * KST + cc;
                uint32_t b0 = *(const uint32_t*)&Kf[bn];
                uint32_t b1 = *(const uint32_t*)&Kf[bn + 8];
                hmma_f16(S[j], qf[kc], b0, b1);
            }
        }

        // Softmax with fixed shift m=0 (shift-invariant, no overflow)
        const bool diag = (t == qt);
        float rs0 = 0.0f, rs1 = 0.0f;
        #pragma unroll
        for (int j = 0; j < 8; j++) {
            #pragma unroll
            for (int e = 0; e < 2; e++) {
                const int kg = k0 + j * 8 + tg * 2 + e;
                float z0 = S[j][e] * CL2;
                float z1 = S[j][2 + e] * CL2;
                if (diag) {
                    if (kg > r0)     z0 = -1e30f;
                    if (kg > r0 + 8) z1 = -1e30f;
                }
                float p0 = ex2(z0);
                float p1 = ex2(z1);
                S[j][e] = p0; S[j][2 + e] = p1;
                rs0 += p0; rs1 += p1;
            }
        }
        l0 += rs0;
        l1 += rs1;

        // P accum -> fp16 A fragments
        uint32_t pf[4][4];
        #pragma unroll
        for (int kc = 0; kc < 4; kc++) {
            const int j0 = 2 * kc, j1 = 2 * kc + 1;
            pf[kc][0] = hpack(S[j0][0], S[j0][1]);
            pf[kc][1] = hpack(S[j0][2], S[j0][3]);
            pf[kc][2] = hpack(S[j1][0], S[j1][1]);
            pf[kc][3] = hpack(S[j1][2], S[j1][3]);
        }

        // GEMM2: O += P . V (single fp16 pass)
        #pragma unroll
        for (int kc = 0; kc < 4; kc++) {
            const int cc = kc * 16 + tg * 2;
            #pragma unroll
            for (int j = 0; j < 8; j++) {
                const int bn = (j * 8 + gq) * KST + cc;
                uint32_t b0 = *(const uint32_t*)&Vf[bn];
                uint32_t b1 = *(const uint32_t*)&Vf[bn + 8];
                hmma_f16(O[j], pf[kc], b0, b1);
            }
        }
        __syncthreads();   // reads of buf done before it is refilled
    }

    // sum l across the 4 quad lanes
    l0 += __shfl_xor_sync(0xffffffffu, l0, 1);
    l0 += __shfl_xor_sync(0xffffffffu, l0, 2);
    l1 += __shfl_xor_sync(0xffffffffu, l1, 1);
    l1 += __shfl_xor_sync(0xffffffffu, l1, 2);

    // Write partial
    const int slot = (b * 64 + qt) * 8 + c;
    float* po = g_po + (size_t)slot * 4096;
    #pragma unroll
    for (int j = 0; j < 8; j++) {
        const int d = j * 8 + tg * 2;
        *(float2*)&po[rloc * 64 + d]       = make_float2(O[j][0], O[j][1]);
        *(float2*)&po[(rloc + 8) * 64 + d] = make_float2(O[j][2], O[j][3]);
    }
    if (tg == 0) {
        g_pl[slot * 64 + rloc]     = l0;
        g_pl[slot * 64 + rloc + 8] = l1;
    }
}

// ---------------------------------------------------------------------------
// Combine: grid (64, 4), 256 threads. Thread = (row, 16-col segment).
// ---------------------------------------------------------------------------
__global__ __launch_bounds__(256) void combine_kernel(float* __restrict__ out)
{
    const int qt = blockIdx.x, b = blockIdx.y;
    const int nc = (qt >> 3) + 1;
    const int tid = threadIdx.x;
    const int row = tid >> 2, seg = (tid & 3) * 16;
    const int bs = (b * 64 + qt) * 8;

    float L = 0.0f;
    float acc[16];
    #pragma unroll
    for (int e = 0; e < 16; e++) acc[e] = 0.0f;

    for (int c = 0; c < nc; c++) {
        L += g_pl[(bs + c) * 64 + row];
        const float* p = g_po + ((size_t)(bs + c) * 64 + row) * 64 + seg;
        #pragma unroll
        for (int e = 0; e < 16; e += 4) {
            float4 v = *(const float4*)(p + e);
            acc[e]     += v.x;
            acc[e + 1] += v.y;
            acc[e + 2] += v.z;
            acc[e + 3] += v.w;
        }
    }
    const float inv = 1.0f / L;
    float* q = out + ((size_t)b * T_ + qt * 64 + row) * 64 + seg;
    #pragma unroll
    for (int e = 0; e < 16; e += 4)
        *(float4*)(q + e) = make_float4(acc[e] * inv, acc[e + 1] * inv,
                                        acc[e + 2] * inv, acc[e + 3] * inv);
}

// ---------------------------------------------------------------------------
extern "C" void kernel_launch(void* const* d_in, const int* in_sizes, int n_in,
                              void* d_out, int out_size)
{
    const float* emb = (const float*)d_in[0];
    const float* Wq  = (const float*)d_in[1];
    const float* Wk  = (const float*)d_in[2];
    const float* Wv  = (const float*)d_in[3];
    float* out = (float*)d_out;

    wsplit_kernel<<<192, 256>>>(Wq, Wk, Wv);

    cudaFuncSetAttribute(proj_kernel, cudaFuncAttributeMaxDynamicSharedMemorySize,
                         PSMEM);
    proj_kernel<<<128, 256, PSMEM>>>(emb);

    const int asmem = 2 * 2 * TILEB * (int)sizeof(__half);
    cudaFuncSetAttribute(attn_kernel, cudaFuncAttributeMaxDynamicSharedMemorySize,
                         asmem);
    attn_kernel<<<4 * 288, 128, asmem>>>();

    dim3 cg(64, B_, 1);
    combine_kernel<<<cg, 256>>>(out);
}

// round 16
// speedup vs baseline: 1.7379x; 1.2034x over previous
#include <cuda_runtime.h>
#include <cuda_bf16.h>
#include <cuda_fp16.h>
#include <cstdint>

#define B_    4
#define T_    4096
#define E_    1024
#define MROWS (B_ * T_)
#define CL2   0.045084220f   // (1/32) * log2(e)

// fp16 planes for attention (single precision pass)
__device__ __half g_qf[MROWS * 64];
__device__ __half g_kf[MROWS * 64];
__device__ __half g_vtf[B_ * 64 * T_];   // V transposed [b][d][t]
// pre-converted W plane (fp16): rows 0-63 = Wq, 64-127 = Wk, 128-191 = Wv
__device__ __half g_wf[192 * E_];
// split-K partials: slot = (b*64 + qt)*8 + c
__device__ float g_po[2048 * 64 * 64];
__device__ float g_pl[2048 * 64];

// ---------------------------------------------------------------------------
__device__ __forceinline__ void hmma_f16(float* c, const uint32_t* a,
                                         uint32_t b0, uint32_t b1) {
    asm volatile("mma.sync.aligned.m16n8k16.row.col.f32.f16.f16.f32 "
                 "{%0,%1,%2,%3}, {%4,%5,%6,%7}, {%8,%9}, {%0,%1,%2,%3};"
                 : "+f"(c[0]), "+f"(c[1]), "+f"(c[2]), "+f"(c[3])
                 : "r"(a[0]), "r"(a[1]), "r"(a[2]), "r"(a[3]),
                   "r"(b0), "r"(b1));
}
__device__ __forceinline__ uint32_t hpack(float a, float b) {
    __half2 h = __floats2half2_rn(a, b);
    return *(uint32_t*)&h;
}
__device__ __forceinline__ float hlo(float x) {
    return x - __half2float(__float2half(x));
}
__device__ __forceinline__ float ex2(float x) {
    float y; asm("ex2.approx.f32 %0, %1;" : "=f"(y) : "f"(x)); return y;
}
__device__ __forceinline__ void cpa(void* dst, const void* src) {
    uint32_t d = (uint32_t)__cvta_generic_to_shared(dst);
    asm volatile("cp.async.cg.shared.global [%0], [%1], 16;"
                 :: "r"(d), "l"(src) : "memory");
}
#define CP_COMMIT() asm volatile("cp.async.commit_group;" ::: "memory")
#define CP_WAIT0()  asm volatile("cp.async.wait_group 0;" ::: "memory")
#define CP_WAIT1()  asm volatile("cp.async.wait_group 1;" ::: "memory")

// ---------------------------------------------------------------------------
// W pre-convert to fp16: 192 rows x 1024. grid 192, 256 threads.
// ---------------------------------------------------------------------------
__global__ __launch_bounds__(256) void wsplit_kernel(
    const float* __restrict__ Wq, const float* __restrict__ Wk,
    const float* __restrict__ Wv)
{
    const int r = blockIdx.x, c = threadIdx.x * 4;
    const float* W = (r < 64) ? Wq : (r < 128) ? Wk : Wv;
    float4 v = *(const float4*)&W[(size_t)(r & 63) * E_ + c];
    *(uint2*)&g_wf[r * E_ + c] =
        make_uint2(hpack(v.x, v.y), hpack(v.z, v.w));
}

// ---------------------------------------------------------------------------
// Merged projection, cp.async double-buffered, fp16 2-term (A = ah + al
// exact fp16 split; W rounded once to fp16 -> only W rounding survives,
// output err ~1.2e-4 < fp16 store quantization).
// grid 128, 256 threads (8 warps). Warp owns 16 rows x all 192 out cols.
// smem: Araw[2] 128x68 fp32 + Bf[2] 192x72 fp16 = 124928 B. 1 CTA/SM
// (register-limited), prefetch of chunk ch+1 overlaps MMA of chunk ch.
// ---------------------------------------------------------------------------
#define PAW 68
#define PST 72
#define ARAW_B 34816
#define BPLANE 27648
#define PSMEM (2 * ARAW_B + 2 * BPLANE)

__global__ __launch_bounds__(256) void proj_kernel(const float* __restrict__ emb)
{
    extern __shared__ char psm[];
    float* Araw0 = (float*)psm;
    float* Araw1 = (float*)(psm + ARAW_B);
    __half* Bf0 = (__half*)(psm + 2 * ARAW_B);
    __half* Bf1 = (__half*)(psm + 2 * ARAW_B + BPLANE);

    const int tid = threadIdx.x, lane = tid & 31, wid = tid >> 5;
    const int gq = lane >> 2, tg = lane & 3;
    const int row0 = blockIdx.x * 128;

    float acc[24][4];
    #pragma unroll
    for (int j = 0; j < 24; j++)
        #pragma unroll
        for (int e = 0; e < 4; e++) acc[j][e] = 0.0f;

    auto issue = [&](int ch) {
        const int bsel = ch & 1;
        float* Ar = bsel ? Araw1 : Araw0;
        __half* Bf = bsel ? Bf1 : Bf0;
        const int k0 = ch * 64;
        #pragma unroll
        for (int it = 0; it < 8; it++) {
            int idx = tid + it * 256;
            int r = idx >> 4, f = idx & 15;
            cpa(&Ar[r * PAW + f * 4],
                &emb[(size_t)(row0 + r) * E_ + k0 + f * 4]);
        }
        #pragma unroll
        for (int it = 0; it < 6; it++) {
            int idx = tid + it * 256;
            int r = idx >> 3, f = idx & 7;
            cpa(&Bf[r * PST + f * 8], &g_wf[(size_t)r * E_ + k0 + f * 8]);
        }
    };

    issue(0);
    CP_COMMIT();

    for (int ch = 0; ch < 16; ch++) {
        if (ch < 15) {
            issue(ch + 1);
            CP_COMMIT();
            CP_WAIT1();
        } else {
            CP_WAIT0();
        }
        __syncthreads();

        const int bsel = ch & 1;
        const float* Ar = bsel ? Araw1 : Araw0;
        const __half* Bf = bsel ? Bf1 : Bf0;
        const int rr = wid * 16 + gq;

        #pragma unroll
        for (int kc = 0; kc < 4; kc++) {
            const int c = kc * 16 + tg * 2;
            float2 x0 = *(const float2*)&Ar[rr * PAW + c];
            float2 x1 = *(const float2*)&Ar[(rr + 8) * PAW + c];
            float2 x2 = *(const float2*)&Ar[rr * PAW + c + 8];
            float2 x3 = *(const float2*)&Ar[(rr + 8) * PAW + c + 8];
            uint32_t ah[4], al[4];
            ah[0] = hpack(x0.x, x0.y);  al[0] = hpack(hlo(x0.x), hlo(x0.y));
            ah[1] = hpack(x1.x, x1.y);  al[1] = hpack(hlo(x1.x), hlo(x1.y));
            ah[2] = hpack(x2.x, x2.y);  al[2] = hpack(hlo(x2.x), hlo(x2.y));
            ah[3] = hpack(x3.x, x3.y);  al[3] = hpack(hlo(x3.x), hlo(x3.y));
            #pragma unroll
            for (int j = 0; j < 24; j++) {
                const int bn = (j * 8 + gq) * PST + c;
                uint32_t b0 = *(const uint32_t*)&Bf[bn];
                uint32_t b1 = *(const uint32_t*)&Bf[bn + 8];
                hmma_f16(acc[j], ah, b0, b1);
                hmma_f16(acc[j], al, b0, b1);
            }
        }
        __syncthreads();
    }

    // Epilogue: fp16 planes for attention
    #pragma unroll
    for (int half = 0; half < 2; half++) {
        const int row = row0 + wid * 16 + gq + half * 8;
        const int b = row >> 12, t = row & (T_ - 1);
        #pragma unroll
        for (int j = 0; j < 24; j++) {
            const int wsel = j >> 3;
            const int d = (j & 7) * 8 + tg * 2;
            const float x0 = acc[j][half * 2 + 0];
            const float x1 = acc[j][half * 2 + 1];
            if (wsel < 2) {
                __half* gf = (wsel == 0) ? g_qf : g_kf;
                *(uint32_t*)&gf[(size_t)row * 64 + d] = hpack(x0, x1);
            } else {
                g_vtf[(size_t)(b * 64 + d) * T_ + t]     = __float2half(x0);
                g_vtf[(size_t)(b * 64 + d + 1) * T_ + t] = __float2half(x1);
            }
        }
    }
}

// ---------------------------------------------------------------------------
// Flash attention, split-K units, m=0 softmax, single-pass fp16 MMA.
// grid 1152 = 4 x 288. Unit = (b, 64-row q-block qt, chunk c of <=8 key
// tiles of 64). 128 threads (4 warps), warp = 16 rows.
// smem: 2 bufs x 2 planes (Kf, Vf) x 64x72 fp16 = 36864 B dynamic.
// ---------------------------------------------------------------------------
#define KST   72
#define TILEB (64 * KST)

__device__ __forceinline__ void attn_issue(__half* buf, int b, size_t bT,
                                           int k0, int tid) {
    __half* Kf = buf;
    __half* Vf = buf + TILEB;
    #pragma unroll
    for (int it = 0; it < 4; it++) {
        int idx = tid + it * 128;
        int r = idx >> 3, f = idx & 7;
        cpa(&Kf[r * KST + f * 8], &g_kf[(bT + k0 + r) * 64 + f * 8]);
        cpa(&Vf[r * KST + f * 8], &g_vtf[(size_t)(b * 64 + r) * T_ + k0 + f * 8]);
    }
}

__global__ __launch_bounds__(128) void attn_kernel()
{
    extern __shared__ __half smd[];

    const int tid = threadIdx.x, lane = tid & 31, wid = tid >> 5;
    const int gq = lane >> 2, tg = lane & 3;

    // decode unit
    const int u = blockIdx.x;
    const int b = u / 288;
    const int r = u - b * 288;
    int gg = 0;
    #pragma unroll
    for (int i = 1; i < 8; i++) if (r >= 4 * i * (i + 1)) gg = i;
    const int off = r - 4 * gg * (gg + 1);
    const int blk = off / (gg + 1);
    const int c   = off - blk * (gg + 1);
    const int qt  = 8 * gg + blk;
    const int t0  = c * 8;
    const int t1  = min(t0 + 8, qt + 1);
    const int q0  = qt * 64;
    const size_t bT = (size_t)b * T_;
    const int rloc = wid * 16 + gq;
    const int r0 = q0 + rloc;

    attn_issue(smd, b, bT, t0 * 64, tid);
    CP_COMMIT();

    // Hoist Q fragments (fp16, single)
    uint32_t qf[4][4];
    #pragma unroll
    for (int kc = 0; kc < 4; kc++) {
        const int cc = kc * 16 + tg * 2;
        const size_t p0 = (bT + r0) * 64 + cc;
        const size_t p1 = (bT + r0 + 8) * 64 + cc;
        qf[kc][0] = *(const uint32_t*)&g_qf[p0];
        qf[kc][1] = *(const uint32_t*)&g_qf[p1];
        qf[kc][2] = *(const uint32_t*)&g_qf[p0 + 8];
        qf[kc][3] = *(const uint32_t*)&g_qf[p1 + 8];
    }

    float O[8][4];
    #pragma unroll
    for (int j = 0; j < 8; j++)
        #pragma unroll
        for (int e = 0; e < 4; e++) O[j][e] = 0.0f;
    float l0 = 0.0f, l1 = 0.0f;

    for (int t = t0; t < t1; t++) {
        const int cur = (t - t0) & 1;
        const __half* buf = smd + cur * 2 * TILEB;
        const __half* Kf = buf;
        const __half* Vf = buf + TILEB;
        const int k0 = t * 64;

        if (t + 1 < t1) {
            attn_issue(smd + (cur ^ 1) * 2 * TILEB, b, bT, (t + 1) * 64, tid);
            CP_COMMIT();
            CP_WAIT1();
        } else {
            CP_WAIT0();
        }
        __syncthreads();

        // GEMM1: S = Q . K^T (single fp16 pass)
        float S[8][4];
        #pragma unroll
        for (int j = 0; j < 8; j++)
            #pragma unroll
            for (int e = 0; e < 4; e++) S[j][e] = 0.0f;
        #pragma unroll
        for (int kc = 0; kc < 4; kc++) {
            const int cc = kc * 16 + tg * 2;
            #pragma unroll
            for (int j = 0; j < 8; j++) {
                const int bn = (j * 8 + gq) * KST + cc;
                uint32_t b0 = *(const uint32_t*)&Kf[bn];
                uint32_t b1 = *(const uint32_t*)&Kf[bn + 8];
                hmma_f16(S[j], qf[kc], b0, b1);
            }
        }

        // Softmax with fixed shift m=0 (shift-invariant, no overflow)
        const bool diag = (t == qt);
        float rs0 = 0.0f, rs1 = 0.0f;
        #pragma unroll
        for (int j = 0; j < 8; j++) {
            #pragma unroll
            for (int e = 0; e < 2; e++) {
                const int kg = k0 + j * 8 + tg * 2 + e;
                float z0 = S[j][e] * CL2;
                float z1 = S[j][2 + e] * CL2;
                if (diag) {
                    if (kg > r0)     z0 = -1e30f;
                    if (kg > r0 + 8) z1 = -1e30f;
                }
                float p0 = ex2(z0);
                float p1 = ex2(z1);
                S[j][e] = p0; S[j][2 + e] = p1;
                rs0 += p0; rs1 += p1;
            }
        }
        l0 += rs0;
        l1 += rs1;

        // P accum -> fp16 A fragments
        uint32_t pf[4][4];
        #pragma unroll
        for (int kc = 0; kc < 4; kc++) {
            const int j0 = 2 * kc, j1 = 2 * kc + 1;
            pf[kc][0] = hpack(S[j0][0], S[j0][1]);
            pf[kc][1] = hpack(S[j0][2], S[j0][3]);
            pf[kc][2] = hpack(S[j1][0], S[j1][1]);
            pf[kc][3] = hpack(S[j1][2], S[j1][3]);
        }

        // GEMM2: O += P . V (single fp16 pass)
        #pragma unroll
        for (int kc = 0; kc < 4; kc++) {
            const int cc = kc * 16 + tg * 2;
            #pragma unroll
            for (int j = 0; j < 8; j++) {
                const int bn = (j * 8 + gq) * KST + cc;
                uint32_t b0 = *(const uint32_t*)&Vf[bn];
                uint32_t b1 = *(const uint32_t*)&Vf[bn + 8];
                hmma_f16(O[j], pf[kc], b0, b1);
            }
        }
        __syncthreads();   // reads of buf done before it is refilled
    }

    // sum l across the 4 quad lanes
    l0 += __shfl_xor_sync(0xffffffffu, l0, 1);
    l0 += __shfl_xor_sync(0xffffffffu, l0, 2);
    l1 += __shfl_xor_sync(0xffffffffu, l1, 1);
    l1 += __shfl_xor_sync(0xffffffffu, l1, 2);

    // Write partial
    const int slot = (b * 64 + qt) * 8 + c;
    float* po = g_po + (size_t)slot * 4096;
    #pragma unroll
    for (int j = 0; j < 8; j++) {
        const int d = j * 8 + tg * 2;
        *(float2*)&po[rloc * 64 + d]       = make_float2(O[j][0], O[j][1]);
        *(float2*)&po[(rloc + 8) * 64 + d] = make_float2(O[j][2], O[j][3]);
    }
    if (tg == 0) {
        g_pl[slot * 64 + rloc]     = l0;
        g_pl[slot * 64 + rloc + 8] = l1;
    }
}

// ---------------------------------------------------------------------------
// Combine: grid (64, 4, 4), 256 threads. Block = (qt, b, 16-col quarter);
// thread = (row, 4 cols). 4x more blocks than before for latency hiding.
// ---------------------------------------------------------------------------
__global__ __launch_bounds__(256) void combine_kernel(float* __restrict__ out)
{
    const int qt = blockIdx.x, b = blockIdx.y, colq = blockIdx.z;
    const int nc = (qt >> 3) + 1;
    const int tid = threadIdx.x;
    const int row = tid >> 2, seg = colq * 16 + (tid & 3) * 4;
    const int bs = (b * 64 + qt) * 8;

    float L = 0.0f;
    float a0 = 0.0f, a1 = 0.0f, a2 = 0.0f, a3 = 0.0f;

    for (int c = 0; c < nc; c++) {
        L += g_pl[(bs + c) * 64 + row];
        const float* p = g_po + ((size_t)(bs + c) * 64 + row) * 64 + seg;
        float4 v = *(const float4*)p;
        a0 += v.x; a1 += v.y; a2 += v.z; a3 += v.w;
    }
    const float inv = 1.0f / L;
    float* q = out + ((size_t)b * T_ + qt * 64 + row) * 64 + seg;
    *(float4*)q = make_float4(a0 * inv, a1 * inv, a2 * inv, a3 * inv);
}

// ---------------------------------------------------------------------------
extern "C" void kernel_launch(void* const* d_in, const int* in_sizes, int n_in,
                              void* d_out, int out_size)
{
    const float* emb = (const float*)d_in[0];
    const float* Wq  = (const float*)d_in[1];
    const float* Wk  = (const float*)d_in[2];
    const float* Wv  = (const float*)d_in[3];
    float* out = (float*)d_out;

    wsplit_kernel<<<192, 256>>>(Wq, Wk, Wv);

    cudaFuncSetAttribute(proj_kernel, cudaFuncAttributeMaxDynamicSharedMemorySize,
                         PSMEM);
    proj_kernel<<<128, 256, PSMEM>>>(emb);

    const int asmem = 2 * 2 * TILEB * (int)sizeof(__half);
    cudaFuncSetAttribute(attn_kernel, cudaFuncAttributeMaxDynamicSharedMemorySize,
                         asmem);
    attn_kernel<<<4 * 288, 128, asmem>>>();

    dim3 cg(64, B_, 4);
    combine_kernel<<<cg, 256>>>(out);
}

// round 17
// speedup vs baseline: 1.8981x; 1.0922x over previous
#include <cuda_runtime.h>
#include <cuda_bf16.h>
#include <cuda_fp16.h>
#include <cstdint>

#define B_    4
#define T_    4096
#define E_    1024
#define MROWS (B_ * T_)
#define CL2   0.045084220f   // (1/32) * log2(e)

// fp16 planes for attention (single precision pass)
__device__ __half g_qf[MROWS * 64];
__device__ __half g_kf[MROWS * 64];
__device__ __half g_vtf[B_ * 64 * T_];   // V transposed [b][d][t]
// pre-converted W plane (fp16): rows 0-63 = Wq, 64-127 = Wk, 128-191 = Wv
__device__ __half g_wf[192 * E_];
// split-K partials: slot = (b*64 + qt)*8 + c
__device__ float g_po[2048 * 64 * 64];
__device__ float g_pl[2048 * 64];

// ---------------------------------------------------------------------------
__device__ __forceinline__ void hmma_f16(float* c, const uint32_t* a,
                                         uint32_t b0, uint32_t b1) {
    asm volatile("mma.sync.aligned.m16n8k16.row.col.f32.f16.f16.f32 "
                 "{%0,%1,%2,%3}, {%4,%5,%6,%7}, {%8,%9}, {%0,%1,%2,%3};"
                 : "+f"(c[0]), "+f"(c[1]), "+f"(c[2]), "+f"(c[3])
                 : "r"(a[0]), "r"(a[1]), "r"(a[2]), "r"(a[3]),
                   "r"(b0), "r"(b1));
}
__device__ __forceinline__ uint32_t hpack(float a, float b) {
    __half2 h = __floats2half2_rn(a, b);
    return *(uint32_t*)&h;
}
__device__ __forceinline__ float ex2(float x) {
    float y; asm("ex2.approx.f32 %0, %1;" : "=f"(y) : "f"(x)); return y;
}
__device__ __forceinline__ void cpa(void* dst, const void* src) {
    uint32_t d = (uint32_t)__cvta_generic_to_shared(dst);
    asm volatile("cp.async.cg.shared.global [%0], [%1], 16;"
                 :: "r"(d), "l"(src) : "memory");
}
#define CP_COMMIT() asm volatile("cp.async.commit_group;" ::: "memory")
#define CP_WAIT0()  asm volatile("cp.async.wait_group 0;" ::: "memory")
#define CP_WAIT1()  asm volatile("cp.async.wait_group 1;" ::: "memory")

// ---------------------------------------------------------------------------
// W pre-convert to fp16: 192 rows x 1024. grid 192, 256 threads.
// ---------------------------------------------------------------------------
__global__ __launch_bounds__(256) void wsplit_kernel(
    const float* __restrict__ Wq, const float* __restrict__ Wk,
    const float* __restrict__ Wv)
{
    const int r = blockIdx.x, c = threadIdx.x * 4;
    const float* W = (r < 64) ? Wq : (r < 128) ? Wk : Wv;
    float4 v = *(const float4*)&W[(size_t)(r & 63) * E_ + c];
    *(uint2*)&g_wf[r * E_ + c] =
        make_uint2(hpack(v.x, v.y), hpack(v.z, v.w));
}

// ---------------------------------------------------------------------------
// Merged projection, cp.async double-buffered, single-pass fp16.
// grid 128, 256 threads (8 warps). Warp owns 16 rows x all 192 out cols.
// smem: Araw[2] 128x68 fp32 + Bf[2] 192x72 fp16 = 124928 B.
// Prefetch of chunk ch+1 overlaps MMA of chunk ch.
// ---------------------------------------------------------------------------
#define PAW 68
#define PST 72
#define ARAW_B 34816
#define BPLANE 27648
#define PSMEM (2 * ARAW_B + 2 * BPLANE)

__global__ __launch_bounds__(256) void proj_kernel(const float* __restrict__ emb)
{
    extern __shared__ char psm[];
    float* Araw0 = (float*)psm;
    float* Araw1 = (float*)(psm + ARAW_B);
    __half* Bf0 = (__half*)(psm + 2 * ARAW_B);
    __half* Bf1 = (__half*)(psm + 2 * ARAW_B + BPLANE);

    const int tid = threadIdx.x, lane = tid & 31, wid = tid >> 5;
    const int gq = lane >> 2, tg = lane & 3;
    const int row0 = blockIdx.x * 128;

    float acc[24][4];
    #pragma unroll
    for (int j = 0; j < 24; j++)
        #pragma unroll
        for (int e = 0; e < 4; e++) acc[j][e] = 0.0f;

    auto issue = [&](int ch) {
        const int bsel = ch & 1;
        float* Ar = bsel ? Araw1 : Araw0;
        __half* Bf = bsel ? Bf1 : Bf0;
        const int k0 = ch * 64;
        #pragma unroll
        for (int it = 0; it < 8; it++) {
            int idx = tid + it * 256;
            int r = idx >> 4, f = idx & 15;
            cpa(&Ar[r * PAW + f * 4],
                &emb[(size_t)(row0 + r) * E_ + k0 + f * 4]);
        }
        #pragma unroll
        for (int it = 0; it < 6; it++) {
            int idx = tid + it * 256;
            int r = idx >> 3, f = idx & 7;
            cpa(&Bf[r * PST + f * 8], &g_wf[(size_t)r * E_ + k0 + f * 8]);
        }
    };

    issue(0);
    CP_COMMIT();

    for (int ch = 0; ch < 16; ch++) {
        if (ch < 15) {
            issue(ch + 1);
            CP_COMMIT();
            CP_WAIT1();
        } else {
            CP_WAIT0();
        }
        __syncthreads();

        const int bsel = ch & 1;
        const float* Ar = bsel ? Araw1 : Araw0;
        const __half* Bf = bsel ? Bf1 : Bf0;
        const int rr = wid * 16 + gq;

        #pragma unroll
        for (int kc = 0; kc < 4; kc++) {
            const int c = kc * 16 + tg * 2;
            float2 x0 = *(const float2*)&Ar[rr * PAW + c];
            float2 x1 = *(const float2*)&Ar[(rr + 8) * PAW + c];
            float2 x2 = *(const float2*)&Ar[rr * PAW + c + 8];
            float2 x3 = *(const float2*)&Ar[(rr + 8) * PAW + c + 8];
            uint32_t ah[4];
            ah[0] = hpack(x0.x, x0.y);
            ah[1] = hpack(x1.x, x1.y);
            ah[2] = hpack(x2.x, x2.y);
            ah[3] = hpack(x3.x, x3.y);
            #pragma unroll
            for (int j = 0; j < 24; j++) {
                const int bn = (j * 8 + gq) * PST + c;
                uint32_t b0 = *(const uint32_t*)&Bf[bn];
                uint32_t b1 = *(const uint32_t*)&Bf[bn + 8];
                hmma_f16(acc[j], ah, b0, b1);
            }
        }
        __syncthreads();
    }

    // Epilogue: fp16 planes for attention
    #pragma unroll
    for (int half = 0; half < 2; half++) {
        const int row = row0 + wid * 16 + gq + half * 8;
        const int b = row >> 12, t = row & (T_ - 1);
        #pragma unroll
        for (int j = 0; j < 24; j++) {
            const int wsel = j >> 3;
            const int d = (j & 7) * 8 + tg * 2;
            const float x0 = acc[j][half * 2 + 0];
            const float x1 = acc[j][half * 2 + 1];
            if (wsel < 2) {
                __half* gf = (wsel == 0) ? g_qf : g_kf;
                *(uint32_t*)&gf[(size_t)row * 64 + d] = hpack(x0, x1);
            } else {
                g_vtf[(size_t)(b * 64 + d) * T_ + t]     = __float2half(x0);
                g_vtf[(size_t)(b * 64 + d + 1) * T_ + t] = __float2half(x1);
            }
        }
    }
}

// ---------------------------------------------------------------------------
// Flash attention, split-K units, m=0 softmax, single-pass fp16 MMA.
// grid 1152 = 4 x 288, HEAVY UNITS FIRST (reversed block order).
// Unit = (b, 64-row q-block qt, chunk c of <=8 key tiles of 64).
// 128 threads (4 warps), warp = 16 rows.
// smem: 2 bufs x 2 planes (Kf, Vf) x 64x72 fp16 = 36864 B dynamic.
// ---------------------------------------------------------------------------
#define KST   72
#define TILEB (64 * KST)

__device__ __forceinline__ void attn_issue(__half* buf, int b, size_t bT,
                                           int k0, int tid) {
    __half* Kf = buf;
    __half* Vf = buf + TILEB;
    #pragma unroll
    for (int it = 0; it < 4; it++) {
        int idx = tid + it * 128;
        int r = idx >> 3, f = idx & 7;
        cpa(&Kf[r * KST + f * 8], &g_kf[(bT + k0 + r) * 64 + f * 8]);
        cpa(&Vf[r * KST + f * 8], &g_vtf[(size_t)(b * 64 + r) * T_ + k0 + f * 8]);
    }
}

__global__ __launch_bounds__(128) void attn_kernel()
{
    extern __shared__ __half smd[];

    const int tid = threadIdx.x, lane = tid & 31, wid = tid >> 5;
    const int gq = lane >> 2, tg = lane & 3;

    // decode unit (reversed: heavy units — large gg — launch first)
    const int u = gridDim.x - 1 - blockIdx.x;
    const int b = u / 288;
    const int r = u - b * 288;
    int gg = 0;
    #pragma unroll
    for (int i = 1; i < 8; i++) if (r >= 4 * i * (i + 1)) gg = i;
    const int off = r - 4 * gg * (gg + 1);
    const int blk = off / (gg + 1);
    const int c   = off - blk * (gg + 1);
    const int qt  = 8 * gg + blk;
    const int t0  = c * 8;
    const int t1  = min(t0 + 8, qt + 1);
    const int q0  = qt * 64;
    const size_t bT = (size_t)b * T_;
    const int rloc = wid * 16 + gq;
    const int r0 = q0 + rloc;

    attn_issue(smd, b, bT, t0 * 64, tid);
    CP_COMMIT();

    // Hoist Q fragments (fp16, single)
    uint32_t qf[4][4];
    #pragma unroll
    for (int kc = 0; kc < 4; kc++) {
        const int cc = kc * 16 + tg * 2;
        const size_t p0 = (bT + r0) * 64 + cc;
        const size_t p1 = (bT + r0 + 8) * 64 + cc;
        qf[kc][0] = *(const uint32_t*)&g_qf[p0];
        qf[kc][1] = *(const uint32_t*)&g_qf[p1];
        qf[kc][2] = *(const uint32_t*)&g_qf[p0 + 8];
        qf[kc][3] = *(const uint32_t*)&g_qf[p1 + 8];
    }

    float O[8][4];
    #pragma unroll
    for (int j = 0; j < 8; j++)
        #pragma unroll
        for (int e = 0; e < 4; e++) O[j][e] = 0.0f;
    float l0 = 0.0f, l1 = 0.0f;

    for (int t = t0; t < t1; t++) {
        const int cur = (t - t0) & 1;
        const __half* buf = smd + cur * 2 * TILEB;
        const __half* Kf = buf;
        const __half* Vf = buf + TILEB;
        const int k0 = t * 64;

        if (t + 1 < t1) {
            attn_issue(smd + (cur ^ 1) * 2 * TILEB, b, bT, (t + 1) * 64, tid);
            CP_COMMIT();
            CP_WAIT1();
        } else {
            CP_WAIT0();
        }
        __syncthreads();

        // GEMM1: S = Q . K^T (single fp16 pass)
        float S[8][4];
        #pragma unroll
        for (int j = 0; j < 8; j++)
            #pragma unroll
            for (int e = 0; e < 4; e++) S[j][e] = 0.0f;
        #pragma unroll
        for (int kc = 0; kc < 4; kc++) {
            const int cc = kc * 16 + tg * 2;
            #pragma unroll
            for (int j = 0; j < 8; j++) {
                const int bn = (j * 8 + gq) * KST + cc;
                uint32_t b0 = *(const uint32_t*)&Kf[bn];
                uint32_t b1 = *(const uint32_t*)&Kf[bn + 8];
                hmma_f16(S[j], qf[kc], b0, b1);
            }
        }

        // Softmax with fixed shift m=0 (shift-invariant, no overflow)
        const bool diag = (t == qt);
        float rs0 = 0.0f, rs1 = 0.0f;
        #pragma unroll
        for (int j = 0; j < 8; j++) {
            #pragma unroll
            for (int e = 0; e < 2; e++) {
                const int kg = k0 + j * 8 + tg * 2 + e;
                float z0 = S[j][e] * CL2;
                float z1 = S[j][2 + e] * CL2;
                if (diag) {
                    if (kg > r0)     z0 = -1e30f;
                    if (kg > r0 + 8) z1 = -1e30f;
                }
                float p0 = ex2(z0);
                float p1 = ex2(z1);
                S[j][e] = p0; S[j][2 + e] = p1;
                rs0 += p0; rs1 += p1;
            }
        }
        l0 += rs0;
        l1 += rs1;

        // P accum -> fp16 A fragments
        uint32_t pf[4][4];
        #pragma unroll
        for (int kc = 0; kc < 4; kc++) {
            const int j0 = 2 * kc, j1 = 2 * kc + 1;
            pf[kc][0] = hpack(S[j0][0], S[j0][1]);
            pf[kc][1] = hpack(S[j0][2], S[j0][3]);
            pf[kc][2] = hpack(S[j1][0], S[j1][1]);
            pf[kc][3] = hpack(S[j1][2], S[j1][3]);
        }

        // GEMM2: O += P . V (single fp16 pass)
        #pragma unroll
        for (int kc = 0; kc < 4; kc++) {
            const int cc = kc * 16 + tg * 2;
            #pragma unroll
            for (int j = 0; j < 8; j++) {
                const int bn = (j * 8 + gq) * KST + cc;
                uint32_t b0 = *(const uint32_t*)&Vf[bn];
                uint32_t b1 = *(const uint32_t*)&Vf[bn + 8];
                hmma_f16(O[j], pf[kc], b0, b1);
            }
        }
        __syncthreads();   // reads of buf done before it is refilled
    }

    // sum l across the 4 quad lanes
    l0 += __shfl_xor_sync(0xffffffffu, l0, 1);
    l0 += __shfl_xor_sync(0xffffffffu, l0, 2);
    l1 += __shfl_xor_sync(0xffffffffu, l1, 1);
    l1 += __shfl_xor_sync(0xffffffffu, l1, 2);

    // Write partial
    const int slot = (b * 64 + qt) * 8 + c;
    float* po = g_po + (size_t)slot * 4096;
    #pragma unroll
    for (int j = 0; j < 8; j++) {
        const int d = j * 8 + tg * 2;
        *(float2*)&po[rloc * 64 + d]       = make_float2(O[j][0], O[j][1]);
        *(float2*)&po[(rloc + 8) * 64 + d] = make_float2(O[j][2], O[j][3]);
    }
    if (tg == 0) {
        g_pl[slot * 64 + rloc]     = l0;
        g_pl[slot * 64 + rloc + 8] = l1;
    }
}

// ---------------------------------------------------------------------------
// Combine: grid (64, 4, 4), 256 threads. Block = (qt, b, 16-col quarter);
// thread = (row, 4 cols).
// ---------------------------------------------------------------------------
__global__ __launch_bounds__(256) void combine_kernel(float* __restrict__ out)
{
    const int qt = blockIdx.x, b = blockIdx.y, colq = blockIdx.z;
    const int nc = (qt >> 3) + 1;
    const int tid = threadIdx.x;
    const int row = tid >> 2, seg = colq * 16 + (tid & 3) * 4;
    const int bs = (b * 64 + qt) * 8;

    float L = 0.0f;
    float a0 = 0.0f, a1 = 0.0f, a2 = 0.0f, a3 = 0.0f;

    for (int c = 0; c < nc; c++) {
        L += g_pl[(bs + c) * 64 + row];
        const float* p = g_po + ((size_t)(bs + c) * 64 + row) * 64 + seg;
        float4 v = *(const float4*)p;
        a0 += v.x; a1 += v.y; a2 += v.z; a3 += v.w;
    }
    const float inv = 1.0f / L;
    float* q = out + ((size_t)b * T_ + qt * 64 + row) * 64 + seg;
    *(float4*)q = make_float4(a0 * inv, a1 * inv, a2 * inv, a3 * inv);
}

// ---------------------------------------------------------------------------
extern "C" void kernel_launch(void* const* d_in, const int* in_sizes, int n_in,
                              void* d_out, int out_size)
{
    const float* emb = (const float*)d_in[0];
    const float* Wq  = (const float*)d_in[1];
    const float* Wk  = (const float*)d_in[2];
    const float* Wv  = (const float*)d_in[3];
    float* out = (float*)d_out;

    wsplit_kernel<<<192, 256>>>(Wq, Wk, Wv);

    cudaFuncSetAttribute(proj_kernel, cudaFuncAttributeMaxDynamicSharedMemorySize,
                         PSMEM);
    proj_kernel<<<128, 256, PSMEM>>>(emb);

    const int asmem = 2 * 2 * TILEB * (int)sizeof(__half);
    cudaFuncSetAttribute(attn_kernel, cudaFuncAttributeMaxDynamicSharedMemorySize,
                         asmem);
    attn_kernel<<<4 * 288, 128, asmem>>>();

    dim3 cg(64, B_, 4);
    combine_kernel<<<cg, 256>>>(out);
}